// round 7
// baseline (speedup 1.0000x reference)
#include <cuda_runtime.h>
#include <math.h>

#define NMAPS 32
#define CDIM 256
#define HW 4096          // 64*64
#define NCELLS 256       // 16*16 cells per map
#define NCHUNK 8         // split-K chunks (32 channels each)
#define THRESH 0.65f

// ---------------- device scratch (no allocations allowed) ----------------
__device__ float g_part[NCHUNK * NMAPS * HW];   // partial dots (ref un-normalized; deferred)
__device__ float g_ssp[NCHUNK * HW];            // partial per-pixel sum-of-squares
__device__ float g_sim[NMAPS * HW];             // pixel-normalized sims (rinv deferred)
__device__ float g_cell_score[NMAPS * NCELLS];  // per-cell max (raw, value only)
__device__ float g_cmin_val[NMAPS * NCELLS];    // per-cell min (raw, value only)

// ---------------------------------------------------------------------------
// K1: split-K partial GEMM, 2-pixel register blocking.
// grid = (64 pixel-tiles, 8 chunks), 256 threads. Thread = (2 pixels, 4 refs).
// ---------------------------------------------------------------------------
__global__ void k_gemm(const float* __restrict__ feat, const float* __restrict__ ref) {
    __shared__ __align__(16) float sref_t[32][32];   // [channel][ref]
    int tid = threadIdx.x;
    int chunk = blockIdx.y;

    for (int i = tid; i < 32 * 32; i += 256) {
        int c = i >> 5, r = i & 31;
        sref_t[c][r] = ref[r * CDIM + chunk * 32 + c];
    }
    __syncthreads();

    int lane = tid & 31;
    int rg = tid >> 5;                   // warp-uniform
    int pix = blockIdx.x * 64 + lane;    // this thread: pix and pix+32
    const float* fp = feat + chunk * 32 * HW + pix;

    float a0 = 0.f, a1 = 0.f, a2 = 0.f, a3 = 0.f;
    float b0 = 0.f, b1 = 0.f, b2 = 0.f, b3 = 0.f;
    float ss0 = 0.f, ss1 = 0.f;
    #pragma unroll
    for (int c = 0; c < 32; c++) {
        float v0 = fp[c * HW];
        float v1 = fp[c * HW + 32];
        float4 r4 = *reinterpret_cast<const float4*>(&sref_t[c][rg * 4]);  // broadcast
        ss0 += v0 * v0;  ss1 += v1 * v1;
        a0 = fmaf(r4.x, v0, a0);  b0 = fmaf(r4.x, v1, b0);
        a1 = fmaf(r4.y, v0, a1);  b1 = fmaf(r4.y, v1, b1);
        a2 = fmaf(r4.z, v0, a2);  b2 = fmaf(r4.z, v1, b2);
        a3 = fmaf(r4.w, v0, a3);  b3 = fmaf(r4.w, v1, b3);
    }
    float* po = g_part + (chunk * NMAPS + rg * 4) * HW + pix;
    po[0] = a0;           po[HW] = a1;           po[2 * HW] = a2;           po[3 * HW] = a3;
    po[32] = b0;          po[HW + 32] = b1;      po[2 * HW + 32] = b2;      po[3 * HW + 32] = b3;
    if (rg == 0) { g_ssp[chunk * HW + pix] = ss0; g_ssp[chunk * HW + pix + 32] = ss1; }
}

// ---------------------------------------------------------------------------
// K1b: combine split-K partials + per-pixel norm. grid = (16, 32 maps), 256 thr.
// Fully coalesced; all traffic L2-resident (~8.5 MB).
// ---------------------------------------------------------------------------
__global__ void k_combine() {
    int pix = blockIdx.x * 256 + threadIdx.x;
    int m = blockIdx.y;
    float ss = 0.f, d = 0.f;
    #pragma unroll
    for (int c = 0; c < NCHUNK; c++) ss += g_ssp[c * HW + pix];
    #pragma unroll
    for (int c = 0; c < NCHUNK; c++) d += g_part[(c * NMAPS + m) * HW + pix];
    g_sim[m * HW + pix] = d * (1.0f / (sqrtf(ss) + 1e-12f));
}

// ---------------------------------------------------------------------------
// K2: VALUE-ONLY per-cell max/min of the bilinear-upsampled 64x64 cell.
// Per eval: 1 FFMA + 2 FMNMX (fma+alu dual pipe) — no index selects.
// Indices are resolved lazily in k_sort for the rare cells that need them.
// grid = (256 cells, 32 maps), 64 threads (thread = ox).
// ---------------------------------------------------------------------------
__global__ void k_cells() {
    int cell = blockIdx.x;
    int m = blockIdx.y;
    int cy = cell >> 4, cx = cell & 15;
    int tid = threadIdx.x;   // = ox

    __shared__ float patch[6][8];
    __shared__ float sH[6][64];
    __shared__ float rmax[2], rmin[2];

    if (tid < 36) {
        int i = tid / 6, j = tid - i * 6;
        int sr = min(max(4 * cy - 1 + i, 0), 63);
        int sc = min(max(4 * cx - 1 + j, 0), 63);
        patch[i][j] = g_sim[m * HW + sr * 64 + sc];
    }
    __syncthreads();

    {
        float fx = ((float)(cx * 64 + tid) - 7.5f) * 0.0625f;
        int jx = (int)floorf(fx);
        jx = min(max(jx, 0), 62);
        float tx = fminf(fmaxf(fx - (float)jx, 0.f), 1.f);
        int lj = jx - (4 * cx - 1);
        float wx0 = 1.0f - tx;
        #pragma unroll
        for (int i = 0; i < 6; i++)
            sH[i][tid] = wx0 * patch[i][lj] + tx * patch[i][lj + 1];
    }
    __syncthreads();

    float bestv = -1e30f, minv = 1e30f;
    #pragma unroll
    for (int s = 0; s < 5; s++) {
        const int seg_len = (s == 0 || s == 4) ? 8 : 16;
        int jy_t = 4 * cy - 1 + s;
        int jy_c = min(max(jy_t, 0), 62);
        int li = jy_c - (4 * cy - 1);
        float ty, step;
        if (jy_t < 0)       { ty = 0.0f; step = 0.0f; }
        else if (jy_t > 62) { ty = 1.0f; step = 0.0f; }
        else                { ty = (s == 0) ? 0.53125f : 0.03125f; step = 0.0625f; }
        float r0 = sH[li][tid], r1 = sH[li + 1][tid];
        #pragma unroll
        for (int k = 0; k < seg_len; k++) {
            float v = (1.0f - ty) * r0 + ty * r1;
            bestv = fmaxf(bestv, v);
            minv  = fminf(minv, v);
            ty += step;
        }
    }
    #pragma unroll
    for (int off = 16; off; off >>= 1) {
        bestv = fmaxf(bestv, __shfl_down_sync(0xFFFFFFFFu, bestv, off));
        minv  = fminf(minv,  __shfl_down_sync(0xFFFFFFFFu, minv,  off));
    }
    int w = tid >> 5;
    if ((tid & 31) == 0) { rmax[w] = bestv; rmin[w] = minv; }
    __syncthreads();
    if (tid == 0) {
        g_cell_score[m * NCELLS + cell] = fmaxf(rmax[0], rmax[1]);
        g_cmin_val[m * NCELLS + cell]   = fminf(rmin[0], rmin[1]);
    }
}

// ---------------------------------------------------------------------------
// K3: per map (32 blocks x 256 thr): compute rinv + gmin; lazily RESOLVE
// argmax/argmin indices by recomputing only candidate cells (bit-identical
// arithmetic: all ty/tx are exact dyadics); then threshold + stable
// descending rank sort + bg write. Output: points [32,256,3] then bg [32,1,2].
// ---------------------------------------------------------------------------
__global__ void k_sort(float* __restrict__ out, const float* __restrict__ ref) {
    int m = blockIdx.x;
    int tid = threadIdx.x;

    __shared__ __align__(16) float skey[256];
    __shared__ float scell[256], scmin[256];
    __shared__ int   sidx[256];
    __shared__ float rrv[256]; __shared__ int rri[256];
    __shared__ float patch[6][8];
    __shared__ float sH[6][64];
    __shared__ float red[8];
    __shared__ float s_rinv;
    __shared__ float s_bgv; __shared__ int s_bgi;

    // ref-norm reciprocal (tree reduce)
    {
        float v = ref[m * CDIM + tid];
        float p = v * v;
        #pragma unroll
        for (int off = 16; off; off >>= 1) p += __shfl_down_sync(0xFFFFFFFFu, p, off);
        if ((tid & 31) == 0) red[tid >> 5] = p;
    }
    scell[tid] = g_cell_score[m * NCELLS + tid];
    scmin[tid] = g_cmin_val[m * NCELLS + tid];
    if (tid == 0) { s_bgv = 1e30f; s_bgi = 0x7FFFFFFF; }
    __syncthreads();
    if (tid == 0) {
        float s = 0.f;
        #pragma unroll
        for (int i = 0; i < 8; i++) s += red[i];
        s_rinv = 1.0f / (sqrtf(s) + 1e-12f);
    }

    // global min value over the map (tree reduce)
    rrv[tid] = scmin[tid];
    #pragma unroll
    for (int s2 = 128; s2 >= 1; s2 >>= 1) {
        __syncthreads();
        if (tid < s2) rrv[tid] = fminf(rrv[tid], rrv[tid + s2]);
    }
    __syncthreads();
    float gmin = rrv[0];
    float rinv = s_rinv;
    __syncthreads();

    // ---- lazy resolve: recompute only cells that need an index ----
    int ox = tid & 63, oq = tid >> 6;    // 4 oy-quarters x 64 ox
    for (int cell = 0; cell < NCELLS; cell++) {
        bool needmax = scell[cell] * rinv > THRESH;
        bool needmin = scmin[cell] <= gmin;
        if (!(needmax || needmin)) continue;          // uniform across block

        int cy = cell >> 4, cx = cell & 15;
        if (tid < 36) {
            int i = tid / 6, j = tid - i * 6;
            int sr = min(max(4 * cy - 1 + i, 0), 63);
            int sc = min(max(4 * cx - 1 + j, 0), 63);
            patch[i][j] = g_sim[m * HW + sr * 64 + sc];
        }
        __syncthreads();
        if (tid < 64) {
            float fx = ((float)(cx * 64 + tid) - 7.5f) * 0.0625f;
            int jx = (int)floorf(fx);
            jx = min(max(jx, 0), 62);
            float tx = fminf(fmaxf(fx - (float)jx, 0.f), 1.f);
            int lj = jx - (4 * cx - 1);
            float wx0 = 1.0f - tx;
            #pragma unroll
            for (int i = 0; i < 6; i++)
                sH[i][tid] = wx0 * patch[i][lj] + tx * patch[i][lj + 1];
        }
        __syncthreads();

        float bestv = -1e30f; int bidx = 0x7FFFFFFF;
        float mnv = 1e30f;  int mnidx = 0x7FFFFFFF;
        #pragma unroll
        for (int k = 0; k < 16; k++) {
            int oy = oq * 16 + k;
            float fy = ((float)(cy * 64 + oy) - 7.5f) * 0.0625f;
            int jy = (int)floorf(fy);
            jy = min(max(jy, 0), 62);
            float ty = fminf(fmaxf(fy - (float)jy, 0.f), 1.f);
            int li = jy - (4 * cy - 1);
            float r0 = sH[li][ox], r1 = sH[li + 1][ox];
            float v = (1.0f - ty) * r0 + ty * r1;
            int idx = oy * 64 + ox;                    // cell-local row-major
            if (v > bestv) { bestv = v; bidx = idx; }  // first occurrence kept
            if (v < mnv)  { mnv = v;  mnidx = idx; }
        }
        // 256-way reduce: max (tie -> smaller idx)
        rrv[tid] = bestv; rri[tid] = bidx;
        #pragma unroll
        for (int s2 = 128; s2 >= 1; s2 >>= 1) {
            __syncthreads();
            if (tid < s2) {
                float ov = rrv[tid + s2]; int oi = rri[tid + s2];
                if (ov > rrv[tid] || (ov == rrv[tid] && oi < rri[tid])) { rrv[tid] = ov; rri[tid] = oi; }
            }
        }
        __syncthreads();
        if (tid == 0 && needmax) sidx[cell] = rri[0];
        __syncthreads();
        // 256-way reduce: min (tie -> smaller idx)
        rrv[tid] = mnv; rri[tid] = mnidx;
        #pragma unroll
        for (int s2 = 128; s2 >= 1; s2 >>= 1) {
            __syncthreads();
            if (tid < s2) {
                float ov = rrv[tid + s2]; int oi = rri[tid + s2];
                if (ov < rrv[tid] || (ov == rrv[tid] && oi < rri[tid])) { rrv[tid] = ov; rri[tid] = oi; }
            }
        }
        __syncthreads();
        if (tid == 0 && needmin) {
            int loc = rri[0];
            int gidx = ((cy * 64 + (loc >> 6)) << 10) + cx * 64 + (loc & 63);  // flat map idx
            float mv = rrv[0];
            if (mv < s_bgv || (mv == s_bgv && gidx < s_bgi)) { s_bgv = mv; s_bgi = gidx; }
        }
        __syncthreads();
    }

    // ---- points: threshold + stable descending rank sort ----
    float score = scell[tid] * rinv;
    int idx = sidx[tid];     // defined for all valid cells (resolved above)
    bool valid = score > THRESH;
    float key = valid ? score : -1.0f;
    skey[tid] = key;
    __syncthreads();

    int rank = 0;
    const float4* sk4 = reinterpret_cast<const float4*>(skey);
    #pragma unroll 8
    for (int q = 0; q < 64; q++) {
        float4 kk = sk4[q];
        int j = q * 4;
        rank += (kk.x > key) || (kk.x == key && (j + 0) < tid);
        rank += (kk.y > key) || (kk.y == key && (j + 1) < tid);
        rank += (kk.z > key) || (kk.z == key && (j + 2) < tid);
        rank += (kk.w > key) || (kk.w == key && (j + 3) < tid);
    }

    int cy = tid >> 4, cx = tid & 15;
    int ly = (idx >> 6) & 63, lx = idx & 63;
    float* po = out + m * (NCELLS * 3) + rank * 3;
    po[0] = valid ? (float)(cx * 64 + lx) : -1.0f;
    po[1] = valid ? (float)(cy * 64 + ly) : -1.0f;
    po[2] = valid ? score : -1.0f;

    if (tid == 0) {
        float* pb = out + NMAPS * NCELLS * 3 + m * 2;
        pb[0] = (float)(s_bgi & 1023);   // x = col
        pb[1] = (float)(s_bgi >> 10);    // y = row
    }
}

// ---------------------------------------------------------------------------
extern "C" void kernel_launch(void* const* d_in, const int* in_sizes, int n_in,
                              void* d_out, int out_size) {
    const float* feat = (const float*)d_in[0];  // [1,256,64,64]
    const float* ref  = (const float*)d_in[1];  // [32,1,256]
    if (n_in >= 2 && in_sizes[0] == NMAPS * CDIM) {  // defensive: order by size
        ref  = (const float*)d_in[0];
        feat = (const float*)d_in[1];
    }
    (void)out_size;

    dim3 g1(64, NCHUNK);
    k_gemm<<<g1, 256>>>(feat, ref);
    dim3 g1b(16, NMAPS);
    k_combine<<<g1b, 256>>>();
    dim3 g2(NCELLS, NMAPS);
    k_cells<<<g2, 64>>>();
    k_sort<<<NMAPS, 256>>>((float*)d_out, ref);
}

// round 8
// speedup vs baseline: 1.2522x; 1.2522x over previous
#include <cuda_runtime.h>
#include <math.h>

#define NMAPS 32
#define CDIM 256
#define HW 4096          // 64*64
#define NCELLS 256       // 16*16 cells per map
#define NCHUNK 8         // split-K chunks (32 channels each)
#define THRESH 0.65f

// ---------------- device scratch (no allocations allowed) ----------------
__device__ float g_part[NCHUNK * NMAPS * HW];   // partial dots (ref un-normalized; deferred)
__device__ float g_ssp[NCHUNK * HW];            // partial per-pixel sum-of-squares
__device__ float g_sim[NMAPS * HW];             // pixel-normalized sims (rinv deferred)
__device__ float g_cell_score[NMAPS * NCELLS];
__device__ int   g_cell_idx[NMAPS * NCELLS];    // ly*64+lx within cell
__device__ float g_cmin_val[NMAPS * NCELLS];
__device__ int   g_cmin_idx[NMAPS * NCELLS];    // gy*1024+gx flat index

// ---------------------------------------------------------------------------
// K1: split-K partial GEMM with smem-staged feat tile (kills the 8x LDG
// redundancy across warps). grid = (64 pixel-tiles, 8 chunks), 256 threads.
// Thread = (2 adjacent pixels, 4 refs). All operand reads are LDS.
// ---------------------------------------------------------------------------
__global__ void k_gemm(const float* __restrict__ feat, const float* __restrict__ ref) {
    __shared__ __align__(16) float sref_t[32][32];   // [channel][ref]
    __shared__ __align__(16) float sfeat[32][64];    // [channel][pixel]
    int tid = threadIdx.x;
    int chunk = blockIdx.y;

    for (int i = tid; i < 32 * 32; i += 256) {
        int c = i >> 5, r = i & 31;
        sref_t[c][r] = ref[r * CDIM + chunk * 32 + c];
    }
    const float* fbase = feat + chunk * 32 * HW + blockIdx.x * 64;
    #pragma unroll
    for (int i = tid; i < 32 * 64; i += 256) {
        int c = i >> 6, p = i & 63;
        sfeat[c][p] = fbase[c * HW + p];            // coalesced 256B rows
    }
    __syncthreads();

    int lane = tid & 31;
    int rg = tid >> 5;                   // warp-uniform
    int px = 2 * lane;                   // pixels px, px+1 (adjacent)

    float a0 = 0.f, a1 = 0.f, a2 = 0.f, a3 = 0.f;
    float b0 = 0.f, b1 = 0.f, b2 = 0.f, b3 = 0.f;
    float ss0 = 0.f, ss1 = 0.f;
    #pragma unroll
    for (int c = 0; c < 32; c++) {
        float2 v = *reinterpret_cast<const float2*>(&sfeat[c][px]);        // LDS.64
        float4 r4 = *reinterpret_cast<const float4*>(&sref_t[c][rg * 4]);  // broadcast LDS.128
        ss0 += v.x * v.x;  ss1 += v.y * v.y;
        a0 = fmaf(r4.x, v.x, a0);  b0 = fmaf(r4.x, v.y, b0);
        a1 = fmaf(r4.y, v.x, a1);  b1 = fmaf(r4.y, v.y, b1);
        a2 = fmaf(r4.z, v.x, a2);  b2 = fmaf(r4.z, v.y, b2);
        a3 = fmaf(r4.w, v.x, a3);  b3 = fmaf(r4.w, v.y, b3);
    }
    int pix = blockIdx.x * 64 + px;
    float* po = g_part + (chunk * NMAPS + rg * 4) * HW + pix;
    *reinterpret_cast<float2*>(po)          = make_float2(a0, b0);
    *reinterpret_cast<float2*>(po + HW)     = make_float2(a1, b1);
    *reinterpret_cast<float2*>(po + 2 * HW) = make_float2(a2, b2);
    *reinterpret_cast<float2*>(po + 3 * HW) = make_float2(a3, b3);
    if (rg == 0)
        *reinterpret_cast<float2*>(&g_ssp[chunk * HW + pix]) = make_float2(ss0, ss1);
}

// ---------------------------------------------------------------------------
// K1b: combine split-K partials + per-pixel norm. grid = (16, 32 maps), 256 thr.
// Fully coalesced; all traffic L2-resident.
// ---------------------------------------------------------------------------
__global__ void k_combine() {
    int pix = blockIdx.x * 256 + threadIdx.x;
    int m = blockIdx.y;
    float ss = 0.f, d = 0.f;
    #pragma unroll
    for (int c = 0; c < NCHUNK; c++) ss += g_ssp[c * HW + pix];
    #pragma unroll
    for (int c = 0; c < NCHUNK; c++) d += g_part[(c * NMAPS + m) * HW + pix];
    g_sim[m * HW + pix] = d * (1.0f / (sqrtf(ss) + 1e-12f));
}

// ---------------------------------------------------------------------------
// K2: per (map, cell) bilinear-upsampled 64x64 cell max/min WITH indices.
// Inner evals use FFMA with compile-time-constant dyadic ty (exact) in the
// form v = r0 + ty*(r1-r0). Clamped edge segments produce 8 identical values
// -> collapsed to a single candidate at the first oy (exact first-occurrence).
// grid = (256 cells, 32 maps), 64 threads (thread = ox).
// ---------------------------------------------------------------------------
#define UPD(V, OY) { float _v = (V); \
    if (_v > bestv) { bestv = _v; bestoy = (OY); } \
    if (_v < minv)  { minv  = _v; minoy  = (OY); } }

#define SEG16(LI, OY0) { \
    float _r0 = col[(LI) * 64]; float _d = col[((LI) + 1) * 64] - _r0; \
    _Pragma("unroll") \
    for (int k = 0; k < 16; k++) UPD(fmaf((float)(1 + 2 * k) * 0.03125f, _d, _r0), (OY0) + k); }

#define SEG8HI(LI, OY0) { \
    float _r0 = col[(LI) * 64]; float _d = col[((LI) + 1) * 64] - _r0; \
    _Pragma("unroll") \
    for (int k = 0; k < 8; k++) UPD(fmaf((float)(17 + 2 * k) * 0.03125f, _d, _r0), (OY0) + k); }

#define SEG8LO(LI, OY0) { \
    float _r0 = col[(LI) * 64]; float _d = col[((LI) + 1) * 64] - _r0; \
    _Pragma("unroll") \
    for (int k = 0; k < 8; k++) UPD(fmaf((float)(1 + 2 * k) * 0.03125f, _d, _r0), (OY0) + k); }

__global__ void k_cells() {
    int cell = blockIdx.x;
    int m = blockIdx.y;
    int cy = cell >> 4, cx = cell & 15;
    int tid = threadIdx.x;   // = ox

    __shared__ float patch[6][8];
    __shared__ float sH[6][64];
    __shared__ float rmaxv[2]; __shared__ int rmaxi[2];
    __shared__ float rminv[2]; __shared__ int rmini[2];

    if (tid < 36) {
        int i = tid / 6, j = tid - i * 6;
        int sr = min(max(4 * cy - 1 + i, 0), 63);
        int sc = min(max(4 * cx - 1 + j, 0), 63);
        patch[i][j] = g_sim[m * HW + sr * 64 + sc];
    }
    __syncthreads();

    {   // x-interp column for this thread's ox (same form as accepted rounds)
        float fx = ((float)(cx * 64 + tid) - 7.5f) * 0.0625f;
        int jx = (int)floorf(fx);
        jx = min(max(jx, 0), 62);
        float tx = fminf(fmaxf(fx - (float)jx, 0.f), 1.f);
        int lj = jx - (4 * cx - 1);
        float wx0 = 1.0f - tx;
        #pragma unroll
        for (int i = 0; i < 6; i++)
            sH[i][tid] = wx0 * patch[i][lj] + tx * patch[i][lj + 1];
    }
    __syncthreads();

    const float* col = &sH[0][tid];    // stride 64 between rows
    float bestv = -1e30f; int bestoy = 0;
    float minv  =  1e30f; int minoy  = 0;

    if (cy == 0) {
        // s=0 clamped: 8 identical evals v = col[1*64]; only oy=0 can win
        UPD(col[64], 0);
        SEG16(1, 8); SEG16(2, 24); SEG16(3, 40); SEG8LO(4, 56);
    } else if (cy == 15) {
        SEG8HI(0, 0);
        SEG16(1, 8); SEG16(2, 24); SEG16(3, 40);
        // s=4 clamped: 8 identical evals v = col[4*64]; only oy=56 can win
        UPD(col[4 * 64], 56);
    } else {
        SEG8HI(0, 0);
        SEG16(1, 8); SEG16(2, 24); SEG16(3, 40); SEG8LO(4, 56);
    }

    int bidx = bestoy * 64 + tid;                              // cell-local row-major
    int midx = ((cy * 64 + minoy) << 10) + cx * 64 + tid;      // global flat
    #pragma unroll
    for (int off = 16; off; off >>= 1) {
        float ov = __shfl_down_sync(0xFFFFFFFFu, bestv, off);
        int   oi = __shfl_down_sync(0xFFFFFFFFu, bidx, off);
        if (ov > bestv || (ov == bestv && oi < bidx)) { bestv = ov; bidx = oi; }
        float mv = __shfl_down_sync(0xFFFFFFFFu, minv, off);
        int   mi = __shfl_down_sync(0xFFFFFFFFu, midx, off);
        if (mv < minv || (mv == minv && mi < midx)) { minv = mv; midx = mi; }
    }
    int w = tid >> 5;
    if ((tid & 31) == 0) { rmaxv[w] = bestv; rmaxi[w] = bidx; rminv[w] = minv; rmini[w] = midx; }
    __syncthreads();
    if (tid == 0) {
        float bv = rmaxv[0]; int bi = rmaxi[0];
        if (rmaxv[1] > bv || (rmaxv[1] == bv && rmaxi[1] < bi)) { bv = rmaxv[1]; bi = rmaxi[1]; }
        float mv = rminv[0]; int mi = rmini[0];
        if (rminv[1] < mv || (rminv[1] == mv && rmini[1] < mi)) { mv = rminv[1]; mi = rmini[1]; }
        g_cell_score[m * NCELLS + cell] = bv;
        g_cell_idx[m * NCELLS + cell]   = bi;
        g_cmin_val[m * NCELLS + cell]   = mv;
        g_cmin_idx[m * NCELLS + cell]   = mi;
    }
}

// ---------------------------------------------------------------------------
// K3: per map: deferred ref-norm scale, threshold, stable descending rank sort
// (unique ranks -> collision-free scatter), bg via parallel tree min-reduce.
// grid = 32 maps, 256 threads. Output: points [32,256,3] then bg [32,1,2].
// ---------------------------------------------------------------------------
__global__ void k_sort(float* __restrict__ out, const float* __restrict__ ref) {
    int m = blockIdx.x;
    int tid = threadIdx.x;

    __shared__ __align__(16) float skey[256];           // 16B-aligned: LDS.128 reads
    __shared__ __align__(16) float sv[256];
    __shared__ int si[256];
    __shared__ float red[8];
    __shared__ float s_rinv;

    // ref-norm reciprocal for this map (tree reduce)
    {
        float v = ref[m * CDIM + tid];
        float p = v * v;
        #pragma unroll
        for (int off = 16; off; off >>= 1) p += __shfl_down_sync(0xFFFFFFFFu, p, off);
        if ((tid & 31) == 0) red[tid >> 5] = p;
    }
    sv[tid] = g_cmin_val[m * NCELLS + tid];
    si[tid] = g_cmin_idx[m * NCELLS + tid];
    __syncthreads();
    if (tid == 0) {
        float s = 0.f;
        #pragma unroll
        for (int i = 0; i < 8; i++) s += red[i];
        s_rinv = 1.0f / (sqrtf(s) + 1e-12f);
    }
    __syncthreads();
    float rinv = s_rinv;

    float score = g_cell_score[m * NCELLS + tid] * rinv;
    int idx = g_cell_idx[m * NCELLS + tid];
    bool valid = score > THRESH;
    float key = valid ? score : -1.0f;
    skey[tid] = key;
    __syncthreads();

    // stable descending rank: count strictly-greater keys + equal keys earlier
    int rank = 0;
    const float4* sk4 = reinterpret_cast<const float4*>(skey);
    #pragma unroll 8
    for (int q = 0; q < 64; q++) {
        float4 kk = sk4[q];
        int j = q * 4;
        rank += (kk.x > key) || (kk.x == key && (j + 0) < tid);
        rank += (kk.y > key) || (kk.y == key && (j + 1) < tid);
        rank += (kk.z > key) || (kk.z == key && (j + 2) < tid);
        rank += (kk.w > key) || (kk.w == key && (j + 3) < tid);
    }

    int cy = tid >> 4, cx = tid & 15;
    int ly = idx >> 6, lx = idx & 63;
    float* po = out + m * (NCELLS * 3) + rank * 3;
    po[0] = valid ? (float)(cx * 64 + lx) : -1.0f;
    po[1] = valid ? (float)(cy * 64 + ly) : -1.0f;
    po[2] = valid ? score : -1.0f;

    // bg: parallel tree min-reduce (ties -> lowest flat index)
    #pragma unroll
    for (int s2 = 128; s2 >= 1; s2 >>= 1) {
        __syncthreads();
        if (tid < s2) {
            float ov = sv[tid + s2]; int oi = si[tid + s2];
            if (ov < sv[tid] || (ov == sv[tid] && oi < si[tid])) { sv[tid] = ov; si[tid] = oi; }
        }
    }
    if (tid == 0) {
        int mi = si[0];
        float* pb = out + NMAPS * NCELLS * 3 + m * 2;
        pb[0] = (float)(mi & 1023);   // x = col
        pb[1] = (float)(mi >> 10);    // y = row
    }
}

// ---------------------------------------------------------------------------
extern "C" void kernel_launch(void* const* d_in, const int* in_sizes, int n_in,
                              void* d_out, int out_size) {
    const float* feat = (const float*)d_in[0];  // [1,256,64,64]
    const float* ref  = (const float*)d_in[1];  // [32,1,256]
    if (n_in >= 2 && in_sizes[0] == NMAPS * CDIM) {  // defensive: order by size
        ref  = (const float*)d_in[0];
        feat = (const float*)d_in[1];
    }
    (void)out_size;

    dim3 g1(64, NCHUNK);
    k_gemm<<<g1, 256>>>(feat, ref);
    dim3 g1b(16, NMAPS);
    k_combine<<<g1b, 256>>>();
    dim3 g2(NCELLS, NMAPS);
    k_cells<<<g2, 64>>>();
    k_sort<<<NMAPS, 256>>>((float*)d_out, ref);
}

// round 9
// speedup vs baseline: 1.9623x; 1.5671x over previous
#include <cuda_runtime.h>
#include <math.h>

#define NMAPS 32
#define CDIM 256
#define HW 4096          // 64*64
#define NCELLS 256       // 16*16 cells per map
#define NCHUNK 8         // split-K chunks (32 channels each)
#define THRESH 0.65f

// ---------------- device scratch (no allocations allowed) ----------------
__device__ float g_part[NCHUNK * NMAPS * HW];   // partial dots (ref un-normalized; deferred)
__device__ float g_ssp[NCHUNK * HW];            // partial per-pixel sum-of-squares
__device__ float g_cell_score[NMAPS * NCELLS];
__device__ int   g_cell_idx[NMAPS * NCELLS];    // ly*64+lx within cell
__device__ float g_cmin_val[NMAPS * NCELLS];
__device__ int   g_cmin_idx[NMAPS * NCELLS];    // gy*1024+gx flat index

// ---------------------------------------------------------------------------
// K1: split-K partial GEMM with smem-staged feat tile (unchanged from R7).
// grid = (64 pixel-tiles, 8 chunks), 256 threads.
// ---------------------------------------------------------------------------
__global__ void k_gemm(const float* __restrict__ feat, const float* __restrict__ ref) {
    __shared__ __align__(16) float sref_t[32][32];   // [channel][ref]
    __shared__ __align__(16) float sfeat[32][64];    // [channel][pixel]
    int tid = threadIdx.x;
    int chunk = blockIdx.y;

    for (int i = tid; i < 32 * 32; i += 256) {
        int c = i >> 5, r = i & 31;
        sref_t[c][r] = ref[r * CDIM + chunk * 32 + c];
    }
    const float* fbase = feat + chunk * 32 * HW + blockIdx.x * 64;
    #pragma unroll
    for (int i = tid; i < 32 * 64; i += 256) {
        int c = i >> 6, p = i & 63;
        sfeat[c][p] = fbase[c * HW + p];
    }
    __syncthreads();

    int lane = tid & 31;
    int rg = tid >> 5;
    int px = 2 * lane;

    float a0 = 0.f, a1 = 0.f, a2 = 0.f, a3 = 0.f;
    float b0 = 0.f, b1 = 0.f, b2 = 0.f, b3 = 0.f;
    float ss0 = 0.f, ss1 = 0.f;
    #pragma unroll
    for (int c = 0; c < 32; c++) {
        float2 v = *reinterpret_cast<const float2*>(&sfeat[c][px]);
        float4 r4 = *reinterpret_cast<const float4*>(&sref_t[c][rg * 4]);
        ss0 += v.x * v.x;  ss1 += v.y * v.y;
        a0 = fmaf(r4.x, v.x, a0);  b0 = fmaf(r4.x, v.y, b0);
        a1 = fmaf(r4.y, v.x, a1);  b1 = fmaf(r4.y, v.y, b1);
        a2 = fmaf(r4.z, v.x, a2);  b2 = fmaf(r4.z, v.y, b2);
        a3 = fmaf(r4.w, v.x, a3);  b3 = fmaf(r4.w, v.y, b3);
    }
    int pix = blockIdx.x * 64 + px;
    float* po = g_part + (chunk * NMAPS + rg * 4) * HW + pix;
    *reinterpret_cast<float2*>(po)          = make_float2(a0, b0);
    *reinterpret_cast<float2*>(po + HW)     = make_float2(a1, b1);
    *reinterpret_cast<float2*>(po + 2 * HW) = make_float2(a2, b2);
    *reinterpret_cast<float2*>(po + 3 * HW) = make_float2(a3, b3);
    if (rg == 0)
        *reinterpret_cast<float2*>(&g_ssp[chunk * HW + pix]) = make_float2(ss0, ss1);
}

// ---------------------------------------------------------------------------
// K2: fused combine + per-cell bilinear max/min with indices.
// grid = (16 cy-rows, 32 maps), 512 threads. Block builds its 6x64 sim row-
// tile straight from the split-K partials; warp w = cell (cy, cx=w); lane
// handles columns ox=lane, lane+32. Y-segments are linear in ty -> max/min
// at segment-endpoint samples (endpoint trick; rounding is monotone).
// ---------------------------------------------------------------------------
#define EP_SEG(R0, R1, TA, TB, OYA, OYB) {                                    \
    float _d = (R1) - (R0);                                                   \
    float _va = fmaf((TA), _d, (R0)), _vb = fmaf((TB), _d, (R0));             \
    float _mx; int _mxo; float _mn; int _mno;                                 \
    if (_vb > _va) { _mx = _vb; _mxo = (OYB); } else { _mx = _va; _mxo = (OYA); } \
    if (_vb < _va) { _mn = _vb; _mno = (OYB); } else { _mn = _va; _mno = (OYA); } \
    if (_mx > bestv) { bestv = _mx; bestoy = _mxo; }                          \
    if (_mn < minv)  { minv  = _mn; minoy  = _mno; } }

#define EP_ONE(V, OY) { float _v = (V);                                       \
    if (_v > bestv) { bestv = _v; bestoy = (OY); }                            \
    if (_v < minv)  { minv  = _v; minoy  = (OY); } }

__global__ __launch_bounds__(512) void k_cells() {
    int cy = blockIdx.x;
    int m  = blockIdx.y;
    int tid = threadIdx.x;

    __shared__ float tile[6][64];    // sim rows 4cy-1..4cy+4 (clamped)

    if (tid < 384) {
        int row = tid >> 6, colc = tid & 63;
        int sr = min(max(4 * cy - 1 + row, 0), 63);
        int pix = sr * 64 + colc;
        float ss = 0.f, d = 0.f;
        #pragma unroll
        for (int c = 0; c < NCHUNK; c++) ss += g_ssp[c * HW + pix];
        #pragma unroll
        for (int c = 0; c < NCHUNK; c++) d += g_part[(c * NMAPS + m) * HW + pix];
        tile[row][colc] = d * (1.0f / (sqrtf(ss) + 1e-12f));
    }
    __syncthreads();

    int cx = tid >> 5;        // warp = cell
    int lane = tid & 31;
    int cyc = (cy == 0) ? 0 : ((cy == 15) ? 2 : 1);

    float colBest[2]; int colBoy[2];
    float colMin[2];  int colMoy[2];

    #pragma unroll
    for (int h = 0; h < 2; h++) {
        int ox = lane + h * 32;
        int gx = cx * 64 + ox;
        float fx = ((float)gx - 7.5f) * 0.0625f;
        int jx = (int)floorf(fx);
        jx = min(max(jx, 0), 62);
        float tx = fminf(fmaxf(fx - (float)jx, 0.f), 1.f);
        float wx0 = 1.0f - tx;
        float v0 = wx0 * tile[0][jx] + tx * tile[0][jx + 1];
        float v1 = wx0 * tile[1][jx] + tx * tile[1][jx + 1];
        float v2 = wx0 * tile[2][jx] + tx * tile[2][jx + 1];
        float v3 = wx0 * tile[3][jx] + tx * tile[3][jx + 1];
        float v4 = wx0 * tile[4][jx] + tx * tile[4][jx + 1];
        float v5 = wx0 * tile[5][jx] + tx * tile[5][jx + 1];

        float bestv = -1e30f; int bestoy = 0;
        float minv  =  1e30f; int minoy  = 0;
        if (cyc == 0) {
            EP_ONE(v1, 0);                                        // clamped: 8 equal evals
            EP_SEG(v1, v2, 0.03125f, 0.96875f, 8, 23);
            EP_SEG(v2, v3, 0.03125f, 0.96875f, 24, 39);
            EP_SEG(v3, v4, 0.03125f, 0.96875f, 40, 55);
            EP_SEG(v4, v5, 0.03125f, 0.46875f, 56, 63);
        } else if (cyc == 2) {
            EP_SEG(v0, v1, 0.53125f, 0.96875f, 0, 7);
            EP_SEG(v1, v2, 0.03125f, 0.96875f, 8, 23);
            EP_SEG(v2, v3, 0.03125f, 0.96875f, 24, 39);
            EP_SEG(v3, v4, 0.03125f, 0.96875f, 40, 55);
            EP_ONE(v4, 56);                                       // clamped tail
        } else {
            EP_SEG(v0, v1, 0.53125f, 0.96875f, 0, 7);
            EP_SEG(v1, v2, 0.03125f, 0.96875f, 8, 23);
            EP_SEG(v2, v3, 0.03125f, 0.96875f, 24, 39);
            EP_SEG(v3, v4, 0.03125f, 0.96875f, 40, 55);
            EP_SEG(v4, v5, 0.03125f, 0.46875f, 56, 63);
        }
        colBest[h] = bestv; colBoy[h] = bestoy;
        colMin[h]  = minv;  colMoy[h] = minoy;
    }

    // merge the thread's two columns (row-major idx tiebreak)
    float bestv = colBest[0]; int bidx = colBoy[0] * 64 + lane;
    {
        int i2 = colBoy[1] * 64 + lane + 32;
        if (colBest[1] > bestv || (colBest[1] == bestv && i2 < bidx)) { bestv = colBest[1]; bidx = i2; }
    }
    float minv = colMin[0];
    int midx = ((cy * 64 + colMoy[0]) << 10) + cx * 64 + lane;
    {
        int i2 = ((cy * 64 + colMoy[1]) << 10) + cx * 64 + lane + 32;
        if (colMin[1] < minv || (colMin[1] == minv && i2 < midx)) { minv = colMin[1]; midx = i2; }
    }

    // warp reduce (cell == warp, so no cross-warp combine)
    #pragma unroll
    for (int off = 16; off; off >>= 1) {
        float ov = __shfl_down_sync(0xFFFFFFFFu, bestv, off);
        int   oi = __shfl_down_sync(0xFFFFFFFFu, bidx, off);
        if (ov > bestv || (ov == bestv && oi < bidx)) { bestv = ov; bidx = oi; }
        float mv = __shfl_down_sync(0xFFFFFFFFu, minv, off);
        int   mi = __shfl_down_sync(0xFFFFFFFFu, midx, off);
        if (mv < minv || (mv == minv && mi < midx)) { minv = mv; midx = mi; }
    }
    if (lane == 0) {
        int cell = cy * 16 + cx;
        g_cell_score[m * NCELLS + cell] = bestv;
        g_cell_idx[m * NCELLS + cell]   = bidx;
        g_cmin_val[m * NCELLS + cell]   = minv;
        g_cmin_idx[m * NCELLS + cell]   = midx;
    }
}

// ---------------------------------------------------------------------------
// K3: grid = 64 blocks x 256 thr. Blocks 0..31: per-map points (deferred
// ref-norm, threshold, stable descending rank scatter). Blocks 32..63: per-map
// bg via parallel tree min-reduce. The halves run concurrently.
// Output: points [32,256,3] then bg [32,1,2].
// ---------------------------------------------------------------------------
__global__ void k_sort(float* __restrict__ out, const float* __restrict__ ref) {
    int tid = threadIdx.x;

    if (blockIdx.x < 32) {
        int m = blockIdx.x;
        __shared__ __align__(16) float skey[256];
        __shared__ float red[8];
        __shared__ float s_rinv;

        {
            float v = ref[m * CDIM + tid];
            float p = v * v;
            #pragma unroll
            for (int off = 16; off; off >>= 1) p += __shfl_down_sync(0xFFFFFFFFu, p, off);
            if ((tid & 31) == 0) red[tid >> 5] = p;
        }
        __syncthreads();
        if (tid == 0) {
            float s = 0.f;
            #pragma unroll
            for (int i = 0; i < 8; i++) s += red[i];
            s_rinv = 1.0f / (sqrtf(s) + 1e-12f);
        }
        __syncthreads();
        float rinv = s_rinv;

        float score = g_cell_score[m * NCELLS + tid] * rinv;
        int idx = g_cell_idx[m * NCELLS + tid];
        bool valid = score > THRESH;
        float key = valid ? score : -1.0f;
        skey[tid] = key;
        __syncthreads();

        int rank = 0;
        const float4* sk4 = reinterpret_cast<const float4*>(skey);
        #pragma unroll 8
        for (int q = 0; q < 64; q++) {
            float4 kk = sk4[q];
            int j = q * 4;
            rank += (kk.x > key) || (kk.x == key && (j + 0) < tid);
            rank += (kk.y > key) || (kk.y == key && (j + 1) < tid);
            rank += (kk.z > key) || (kk.z == key && (j + 2) < tid);
            rank += (kk.w > key) || (kk.w == key && (j + 3) < tid);
        }

        int cy = tid >> 4, cx = tid & 15;
        int ly = idx >> 6, lx = idx & 63;
        float* po = out + m * (NCELLS * 3) + rank * 3;
        po[0] = valid ? (float)(cx * 64 + lx) : -1.0f;
        po[1] = valid ? (float)(cy * 64 + ly) : -1.0f;
        po[2] = valid ? score : -1.0f;
    } else {
        int m = blockIdx.x - 32;
        __shared__ __align__(16) float sv[256];
        __shared__ int si[256];
        sv[tid] = g_cmin_val[m * NCELLS + tid];
        si[tid] = g_cmin_idx[m * NCELLS + tid];
        #pragma unroll
        for (int s2 = 128; s2 >= 1; s2 >>= 1) {
            __syncthreads();
            if (tid < s2) {
                float ov = sv[tid + s2]; int oi = si[tid + s2];
                if (ov < sv[tid] || (ov == sv[tid] && oi < si[tid])) { sv[tid] = ov; si[tid] = oi; }
            }
        }
        if (tid == 0) {
            int mi = si[0];
            float* pb = out + NMAPS * NCELLS * 3 + m * 2;
            pb[0] = (float)(mi & 1023);   // x = col
            pb[1] = (float)(mi >> 10);    // y = row
        }
    }
}

// ---------------------------------------------------------------------------
extern "C" void kernel_launch(void* const* d_in, const int* in_sizes, int n_in,
                              void* d_out, int out_size) {
    const float* feat = (const float*)d_in[0];  // [1,256,64,64]
    const float* ref  = (const float*)d_in[1];  // [32,1,256]
    if (n_in >= 2 && in_sizes[0] == NMAPS * CDIM) {  // defensive: order by size
        ref  = (const float*)d_in[0];
        feat = (const float*)d_in[1];
    }
    (void)out_size;

    dim3 g1(64, NCHUNK);
    k_gemm<<<g1, 256>>>(feat, ref);
    dim3 g2(16, NMAPS);
    k_cells<<<g2, 512>>>();
    k_sort<<<64, 256>>>((float*)d_out, ref);
}